// round 4
// baseline (speedup 1.0000x reference)
#include <cuda_runtime.h>
#include <math.h>

// ---------------------------------------------------------------------------
// DBASolver: B=16, N=131072, C=2, P=6.
// Kernel 1 (pass1): software-pipelined per-node pass -> scratch + 27-scalar
//   per-batch reduction; LAST block finishes reduction + damped 6x6 solves
//   (all 16 batches in parallel threads) and writes delta_pose.
// Kernel 2 (depth): delta_depth = inv_H_dd * (g_d - H_pd . pose), vectorized.
// ---------------------------------------------------------------------------

#define MAXB 16
#define MAXN 131072
#define ITER 8
#define TPB  256
#define MAXCHUNKS 256

// per-node scratch: {hpd0..3} {hpd4,hpd5,g_d,inv}
__device__ float4   g_scratch[(size_t)MAXB * MAXN * 2];
__device__ float    g_partial[(size_t)MAXB * MAXCHUNKS * 27];
__device__ float    g_pose[MAXB * 6];
__device__ int      g_nanflag;
__device__ unsigned g_done;   // zero-init; atomicInc wraps back to 0 each launch

struct NodeIn {
    float4 a, b, c;   // J_p 12 floats
    float2 rv, wv, jd;
};

__device__ __forceinline__ NodeIn load_node(
    size_t idx,
    const float4* __restrict__ Jp4, const float2* __restrict__ r2,
    const float2* __restrict__ w2,  const float2* __restrict__ jd2)
{
    NodeIn n;
    n.a  = __ldcs(&Jp4[idx * 3 + 0]);
    n.b  = __ldcs(&Jp4[idx * 3 + 1]);
    n.c  = __ldcs(&Jp4[idx * 3 + 2]);
    n.rv = __ldcs(&r2[idx]);
    n.wv = __ldcs(&w2[idx]);
    n.jd = __ldcs(&jd2[idx]);
    return n;
}

__device__ __forceinline__ void compute_node(
    const NodeIn& nd, size_t idx, float safe_l, float acc[27])
{
    float conf = nd.wv.x, nl = nd.wv.y;
    float jp0[6] = { nd.a.x, nd.a.y, nd.a.z, nd.a.w, nd.b.x, nd.b.y };
    float jp1[6] = { nd.b.z, nd.b.w, nd.c.x, nd.c.y, nd.c.z, nd.c.w };
    float2 rv = nd.rv, jdv = nd.jd;

    float hpd[6];
#pragma unroll
    for (int p = 0; p < 6; p++)
        hpd[p] = conf * (jp0[p] * jdv.x + jp1[p] * jdv.y);

    float hdd = conf * (jdv.x * jdv.x + jdv.y * jdv.y);
    float gd  = conf * (jdv.x * rv.x  + jdv.y * rv.y);
    float inv = 1.0f / fmaxf(hdd + safe_l + nl + 1e-4f, 1e-4f);

    float t[6], cjp0[6], cjp1[6];
#pragma unroll
    for (int p = 0; p < 6; p++) {
        t[p]    = inv  * hpd[p];
        cjp0[p] = conf * jp0[p];
        cjp1[p] = conf * jp1[p];
    }

    int k = 0;
#pragma unroll
    for (int p = 0; p < 6; p++) {
#pragma unroll
        for (int q = p; q < 6; q++) {
            float a = acc[k];
            a = fmaf(cjp0[p], jp0[q], a);
            a = fmaf(cjp1[p], jp1[q], a);
            a = fmaf(-t[p],   hpd[q], a);
            acc[k++] = a;
        }
    }
#pragma unroll
    for (int p = 0; p < 6; p++) {
        float gp = conf * (jp0[p] * rv.x + jp1[p] * rv.y);
        acc[21 + p] += gp - t[p] * gd;
    }

    g_scratch[idx * 2 + 0] = make_float4(hpd[0], hpd[1], hpd[2], hpd[3]);
    g_scratch[idx * 2 + 1] = make_float4(hpd[4], hpd[5], gd, inv);
}

__global__ void __launch_bounds__(TPB)
pass1_kernel(const float* __restrict__ r, const float* __restrict__ w,
             const float* __restrict__ Jp, const float* __restrict__ Jd,
             const float* __restrict__ lmbda, const int* __restrict__ iter_idx,
             float* __restrict__ out, int N, int B)
{
    const int b = blockIdx.y;
    const size_t bn0 = (size_t)b * N;
    const size_t base = (size_t)blockIdx.x * (TPB * ITER);

    float lm = lmbda[b];
    float safe_l = isnan(lm) ? 100.0f : lm;
    safe_l = fmaxf(safe_l, 0.001f);

    const float4* __restrict__ Jp4 = (const float4*)Jp;
    const float2* __restrict__ r2  = (const float2*)r;
    const float2* __restrict__ w2  = (const float2*)w;
    const float2* __restrict__ jd2 = (const float2*)Jd;

    float acc[27];
#pragma unroll
    for (int i = 0; i < 27; i++) acc[i] = 0.0f;

    if (base + (size_t)(TPB * ITER) <= (size_t)N) {
        // software pipeline: next iter's loads issue before current compute
        size_t n0 = bn0 + base + threadIdx.x;
        NodeIn cur = load_node(n0, Jp4, r2, w2, jd2);
#pragma unroll
        for (int it = 0; it < ITER; it++) {
            NodeIn nxt;
            if (it + 1 < ITER)
                nxt = load_node(n0 + (size_t)(it + 1) * TPB, Jp4, r2, w2, jd2);
            compute_node(cur, n0 + (size_t)it * TPB, safe_l, acc);
            cur = nxt;
        }
    } else {
#pragma unroll
        for (int it = 0; it < ITER; it++) {
            size_t n = base + (size_t)it * TPB + threadIdx.x;
            if (n < (size_t)N) {
                NodeIn nd = load_node(bn0 + n, Jp4, r2, w2, jd2);
                compute_node(nd, bn0 + n, safe_l, acc);
            }
        }
    }

    // warp reduce 27 values
#pragma unroll
    for (int i = 0; i < 27; i++) {
#pragma unroll
        for (int off = 16; off > 0; off >>= 1)
            acc[i] += __shfl_down_sync(0xFFFFFFFFu, acc[i], off);
    }

    __shared__ float sred[TPB / 32][27];
    int warp = threadIdx.x >> 5, lane = threadIdx.x & 31;
    if (lane == 0) {
#pragma unroll
        for (int i = 0; i < 27; i++) sred[warp][i] = acc[i];
    }
    __syncthreads();

    const int nchunks = gridDim.x;
    if (threadIdx.x < 27) {
        float s = 0.0f;
#pragma unroll
        for (int wd = 0; wd < TPB / 32; wd++) s += sred[wd][threadIdx.x];
        g_partial[((size_t)b * nchunks + blockIdx.x) * 27 + threadIdx.x] = s;
    }
    __syncthreads();

    // ---- last block: finish reduction + solve all batches -----------------
    __shared__ bool s_last;
    if (threadIdx.x == 0) {
        __threadfence();
        unsigned total = gridDim.x * gridDim.y;
        unsigned old = atomicInc(&g_done, total - 1);
        s_last = (old == total - 1);
    }
    __syncthreads();
    if (!s_last) return;

    __shared__ float sH[MAXB][27];
    __shared__ int   s_nan;
    int t = threadIdx.x;
    if (t == 0) s_nan = 0;

    // 432 slots: [batch][27], each sums nchunks partials
    for (int slot = t; slot < B * 27; slot += TPB) {
        int bb = slot / 27, i = slot % 27;
        float s = 0.0f;
        for (int c = 0; c < nchunks; c++)
            s += g_partial[((size_t)bb * nchunks + c) * 27 + i];
        sH[bb][i] = s;
    }
    __syncthreads();

    float pose[6];
    int bb = t;
    if (bb < B) {
        float lm2 = lmbda[bb];
        float sl = isnan(lm2) ? 100.0f : lm2;
        sl = fmaxf(sl, 0.001f);

        float H[6][6], g[6];
        int k = 0;
        for (int p = 0; p < 6; p++)
            for (int q = p; q < 6; q++) { float v = sH[bb][k++]; H[p][q] = v; H[q][p] = v; }
        for (int p = 0; p < 6; p++) g[p] = sH[bb][21 + p];

        for (int i = 0; i < 6; i++) H[i][i] += sl;

        if (iter_idx[0] >= 2) {
            for (int p = 3; p < 6; p++) g[p] = 0.0f;
            for (int p = 3; p < 6; p++)
                for (int q = 3; q < 6; q++) H[p][q] += 1.0e8f;
        }
        for (int i = 0; i < 6; i++) H[i][i] += 1.0f;
        for (int i = 0; i < 6; i++) H[i][i] += 0.01f * H[i][i];

        // 6x6 solve, double, partial pivoting, reciprocal-hoisted
        double A[6][7];
        for (int i = 0; i < 6; i++) {
            for (int j = 0; j < 6; j++) A[i][j] = (double)H[i][j];
            A[i][6] = (double)g[i];
        }
        for (int c = 0; c < 6; c++) {
            int piv = c; double mx = fabs(A[c][c]);
            for (int rr = c + 1; rr < 6; rr++) {
                double a = fabs(A[rr][c]);
                if (a > mx) { mx = a; piv = rr; }
            }
            if (piv != c) {
                for (int j = c; j < 7; j++) {
                    double tmp = A[c][j]; A[c][j] = A[piv][j]; A[piv][j] = tmp;
                }
            }
            double dinv = 1.0 / A[c][c];
            for (int rr = c + 1; rr < 6; rr++) {
                double f = A[rr][c] * dinv;
                for (int j = c; j < 7; j++) A[rr][j] -= f * A[c][j];
            }
        }
        double x[6];
        for (int i = 5; i >= 0; i--) {
            double s = A[i][6];
            for (int j = i + 1; j < 6; j++) s -= A[i][j] * x[j];
            x[i] = s / A[i][i];
        }

        bool anynan = false;
        for (int p = 0; p < 6; p++) {
            pose[p] = (float)x[p];
            g_pose[bb * 6 + p] = pose[p];   // raw pose feeds depth pass
            if (isnan(pose[p])) anynan = true;
        }
        if (anynan) atomicOr(&s_nan, 1);
    }
    __syncthreads();

    if (t == 0) g_nanflag = s_nan;
    if (bb < B) {
        for (int p = 0; p < 6; p++) {
            float v = fminf(fmaxf(pose[p], -2.0f), 2.0f);
            out[bb * 6 + p] = s_nan ? 0.0f : v;
        }
    }
}

#define DPT 4   // nodes per thread in depth pass

__global__ void __launch_bounds__(TPB)
depth_kernel(float* __restrict__ out, int N, int B)
{
    size_t total = (size_t)B * N;
    size_t i0 = ((size_t)blockIdx.x * TPB + threadIdx.x) * DPT;
    if (i0 >= total) return;

    int nanf = g_nanflag;
    float dd[DPT];

    bool grouped = ((N & (DPT - 1)) == 0);
    int b_grp = grouped ? (int)(i0 / (size_t)N) : 0;
    float pg[6];
    if (grouped) {
#pragma unroll
        for (int p = 0; p < 6; p++) pg[p] = g_pose[b_grp * 6 + p];
    }

#pragma unroll
    for (int kk = 0; kk < DPT; kk++) {
        size_t idx = i0 + kk;
        if (idx >= total) { dd[kk] = 0.0f; continue; }

        float4 s0 = __ldcs(&g_scratch[idx * 2 + 0]);
        float4 s1 = __ldcs(&g_scratch[idx * 2 + 1]);

        float p0, p1, p2, p3, p4, p5;
        if (grouped) {
            p0 = pg[0]; p1 = pg[1]; p2 = pg[2]; p3 = pg[3]; p4 = pg[4]; p5 = pg[5];
        } else {
            int b = (int)(idx / (size_t)N);
            p0 = g_pose[b * 6 + 0]; p1 = g_pose[b * 6 + 1]; p2 = g_pose[b * 6 + 2];
            p3 = g_pose[b * 6 + 3]; p4 = g_pose[b * 6 + 4]; p5 = g_pose[b * 6 + 5];
        }

        float v = s0.x * p0 + s0.y * p1 + s0.z * p2
                + s0.w * p3 + s1.x * p4 + s1.y * p5;
        float d = s1.w * (s1.z - v);
        d = fminf(fmaxf(d, -5.0f), 5.0f);
        dd[kk] = nanf ? 0.0f : d;
    }

    float* dst = out + (size_t)B * 6 + i0;
    if (i0 + DPT <= total) {
        if ((((size_t)B * 6 + i0) & 3) == 0) {
            *(float4*)dst = make_float4(dd[0], dd[1], dd[2], dd[3]);
        } else {
#pragma unroll
            for (int kk = 0; kk < DPT; kk++) dst[kk] = dd[kk];
        }
    } else {
        for (int kk = 0; kk < DPT && i0 + kk < total; kk++) dst[kk] = dd[kk];
    }
}

extern "C" void kernel_launch(void* const* d_in, const int* in_sizes, int n_in,
                              void* d_out, int out_size)
{
    const float* r      = (const float*)d_in[0];
    const float* w      = (const float*)d_in[1];
    const float* Jp     = (const float*)d_in[2];
    const float* Jd     = (const float*)d_in[3];
    const float* lmbda  = (const float*)d_in[4];
    const int*   iter_i = (const int*)d_in[5];
    float* out = (float*)d_out;

    int B = in_sizes[4];
    int N = in_sizes[0] / (2 * B);

    int tile   = TPB * ITER;
    int chunks = (N + tile - 1) / tile;

    dim3 g1(chunks, B);
    pass1_kernel<<<g1, TPB>>>(r, w, Jp, Jd, lmbda, iter_i, out, N, B);

    size_t total = (size_t)B * N;
    size_t tpg = (size_t)TPB * DPT;
    int blocks = (int)((total + tpg - 1) / tpg);
    depth_kernel<<<blocks, TPB>>>(out, N, B);
}

// round 5
// speedup vs baseline: 1.1305x; 1.1305x over previous
#include <cuda_runtime.h>
#include <math.h>

// ---------------------------------------------------------------------------
// DBASolver: B=16, N=131072, C=2, P=6.
// Kernel 1 (pass1): per-node H_pd/g_d/inv -> SoA scratch + 27-scalar per-batch
//   reduction; LAST block finishes reduction + damped 6x6 solves, writes pose.
// Kernel 2 (depth): delta_depth = inv * (g_d - H_pd . pose), fully coalesced.
// ---------------------------------------------------------------------------

#define MAXB 16
#define MAXN 131072
#define ITER 8
#define TPB  256
#define MAXCHUNKS 256

// SoA per-node scratch: s0 = {hpd0..3}, s1 = {hpd4, hpd5, g_d, inv}
__device__ float4   g_s0[(size_t)MAXB * MAXN];
__device__ float4   g_s1[(size_t)MAXB * MAXN];
__device__ float    g_partial[(size_t)MAXB * MAXCHUNKS * 27];
__device__ float    g_pose[MAXB * 6];
__device__ int      g_nanflag;
__device__ unsigned g_done;   // zero-init; atomicInc wraps to 0 each launch

__device__ __forceinline__ void node_body(
    size_t idx, float safe_l,
    const float4* __restrict__ Jp4, const float2* __restrict__ r2,
    const float2* __restrict__ w2,  const float2* __restrict__ jd2,
    float acc[27])
{
    float4 jpA = __ldcs(&Jp4[idx * 3 + 0]);
    float4 jpB = __ldcs(&Jp4[idx * 3 + 1]);
    float4 jpC = __ldcs(&Jp4[idx * 3 + 2]);
    float2 rv  = __ldcs(&r2[idx]);
    float2 wv  = __ldcs(&w2[idx]);
    float2 jdv = __ldcs(&jd2[idx]);

    float conf = wv.x, nl = wv.y;
    float jp0[6] = { jpA.x, jpA.y, jpA.z, jpA.w, jpB.x, jpB.y };
    float jp1[6] = { jpB.z, jpB.w, jpC.x, jpC.y, jpC.z, jpC.w };

    float hpd[6];
#pragma unroll
    for (int p = 0; p < 6; p++)
        hpd[p] = conf * (jp0[p] * jdv.x + jp1[p] * jdv.y);

    float hdd = conf * (jdv.x * jdv.x + jdv.y * jdv.y);
    float gd  = conf * (jdv.x * rv.x  + jdv.y * rv.y);
    float inv = 1.0f / fmaxf(hdd + safe_l + nl + 1e-4f, 1e-4f);

    float t[6], cjp0[6], cjp1[6];
#pragma unroll
    for (int p = 0; p < 6; p++) {
        t[p]    = inv  * hpd[p];
        cjp0[p] = conf * jp0[p];
        cjp1[p] = conf * jp1[p];
    }

    int k = 0;
#pragma unroll
    for (int p = 0; p < 6; p++) {
#pragma unroll
        for (int q = p; q < 6; q++) {
            float a = acc[k];
            a = fmaf(cjp0[p], jp0[q], a);
            a = fmaf(cjp1[p], jp1[q], a);
            a = fmaf(-t[p],   hpd[q], a);
            acc[k++] = a;
        }
    }
#pragma unroll
    for (int p = 0; p < 6; p++) {
        float gp = conf * (jp0[p] * rv.x + jp1[p] * rv.y);
        acc[21 + p] += gp - t[p] * gd;
    }

    // SoA stores: 16B lane stride -> fully coalesced
    g_s0[idx] = make_float4(hpd[0], hpd[1], hpd[2], hpd[3]);
    g_s1[idx] = make_float4(hpd[4], hpd[5], gd, inv);
}

__global__ void __launch_bounds__(TPB)
pass1_kernel(const float* __restrict__ r, const float* __restrict__ w,
             const float* __restrict__ Jp, const float* __restrict__ Jd,
             const float* __restrict__ lmbda, const int* __restrict__ iter_idx,
             float* __restrict__ out, int N, int B)
{
    const int b = blockIdx.y;
    const size_t bn0 = (size_t)b * N;
    const size_t base = (size_t)blockIdx.x * (TPB * ITER);

    float lm = lmbda[b];
    float safe_l = isnan(lm) ? 100.0f : lm;
    safe_l = fmaxf(safe_l, 0.001f);

    const float4* __restrict__ Jp4 = (const float4*)Jp;
    const float2* __restrict__ r2  = (const float2*)r;
    const float2* __restrict__ w2  = (const float2*)w;
    const float2* __restrict__ jd2 = (const float2*)Jd;

    float acc[27];
#pragma unroll
    for (int i = 0; i < 27; i++) acc[i] = 0.0f;

    if (base + (size_t)(TPB * ITER) <= (size_t)N) {
#pragma unroll
        for (int it = 0; it < ITER; it++) {
            size_t n = base + (size_t)it * TPB + threadIdx.x;
            node_body(bn0 + n, safe_l, Jp4, r2, w2, jd2, acc);
        }
    } else {
#pragma unroll
        for (int it = 0; it < ITER; it++) {
            size_t n = base + (size_t)it * TPB + threadIdx.x;
            if (n < (size_t)N)
                node_body(bn0 + n, safe_l, Jp4, r2, w2, jd2, acc);
        }
    }

    // warp reduce 27 values
#pragma unroll
    for (int i = 0; i < 27; i++) {
#pragma unroll
        for (int off = 16; off > 0; off >>= 1)
            acc[i] += __shfl_down_sync(0xFFFFFFFFu, acc[i], off);
    }

    __shared__ float sred[TPB / 32][27];
    int warp = threadIdx.x >> 5, lane = threadIdx.x & 31;
    if (lane == 0) {
#pragma unroll
        for (int i = 0; i < 27; i++) sred[warp][i] = acc[i];
    }
    __syncthreads();

    const int nchunks = gridDim.x;
    if (threadIdx.x < 27) {
        float s = 0.0f;
#pragma unroll
        for (int wd = 0; wd < TPB / 32; wd++) s += sred[wd][threadIdx.x];
        g_partial[((size_t)b * nchunks + blockIdx.x) * 27 + threadIdx.x] = s;
    }
    __syncthreads();

    // ---- last block: finish reduction + solve all batches -----------------
    __shared__ bool s_last;
    if (threadIdx.x == 0) {
        __threadfence();
        unsigned total = gridDim.x * gridDim.y;
        unsigned old = atomicInc(&g_done, total - 1);
        s_last = (old == total - 1);
    }
    __syncthreads();
    if (!s_last) return;

    __shared__ float sH[MAXB][27];
    __shared__ int   s_nan;
    int t = threadIdx.x;
    if (t == 0) s_nan = 0;

    for (int slot = t; slot < B * 27; slot += TPB) {
        int bb = slot / 27, i = slot % 27;
        float s = 0.0f;
        for (int c = 0; c < nchunks; c++)
            s += g_partial[((size_t)bb * nchunks + c) * 27 + i];
        sH[bb][i] = s;
    }
    __syncthreads();

    float pose[6];
    int bb = t;
    if (bb < B) {
        float lm2 = lmbda[bb];
        float sl = isnan(lm2) ? 100.0f : lm2;
        sl = fmaxf(sl, 0.001f);

        float H[6][6], g[6];
        int k = 0;
        for (int p = 0; p < 6; p++)
            for (int q = p; q < 6; q++) { float v = sH[bb][k++]; H[p][q] = v; H[q][p] = v; }
        for (int p = 0; p < 6; p++) g[p] = sH[bb][21 + p];

        for (int i = 0; i < 6; i++) H[i][i] += sl;

        if (iter_idx[0] >= 2) {
            for (int p = 3; p < 6; p++) g[p] = 0.0f;
            for (int p = 3; p < 6; p++)
                for (int q = 3; q < 6; q++) H[p][q] += 1.0e8f;
        }
        for (int i = 0; i < 6; i++) H[i][i] += 1.0f;
        for (int i = 0; i < 6; i++) H[i][i] += 0.01f * H[i][i];

        // 6x6 solve, double, partial pivoting
        double A[6][7];
        for (int i = 0; i < 6; i++) {
            for (int j = 0; j < 6; j++) A[i][j] = (double)H[i][j];
            A[i][6] = (double)g[i];
        }
        for (int c = 0; c < 6; c++) {
            int piv = c; double mx = fabs(A[c][c]);
            for (int rr = c + 1; rr < 6; rr++) {
                double a = fabs(A[rr][c]);
                if (a > mx) { mx = a; piv = rr; }
            }
            if (piv != c) {
                for (int j = c; j < 7; j++) {
                    double tmp = A[c][j]; A[c][j] = A[piv][j]; A[piv][j] = tmp;
                }
            }
            double dinv = 1.0 / A[c][c];
            for (int rr = c + 1; rr < 6; rr++) {
                double f = A[rr][c] * dinv;
                for (int j = c; j < 7; j++) A[rr][j] -= f * A[c][j];
            }
        }
        double x[6];
        for (int i = 5; i >= 0; i--) {
            double s = A[i][6];
            for (int j = i + 1; j < 6; j++) s -= A[i][j] * x[j];
            x[i] = s / A[i][i];
        }

        bool anynan = false;
        for (int p = 0; p < 6; p++) {
            pose[p] = (float)x[p];
            g_pose[bb * 6 + p] = pose[p];   // raw pose feeds depth pass
            if (isnan(pose[p])) anynan = true;
        }
        if (anynan) atomicOr(&s_nan, 1);
    }
    __syncthreads();

    if (t == 0) g_nanflag = s_nan;
    if (bb < B) {
        for (int p = 0; p < 6; p++) {
            float v = fminf(fmaxf(pose[p], -2.0f), 2.0f);
            out[bb * 6 + p] = s_nan ? 0.0f : v;
        }
    }
}

#define DPT 4   // nodes per thread in depth pass (TPB-strided -> coalesced)

__global__ void __launch_bounds__(TPB)
depth_kernel(float* __restrict__ out, int N, int B)
{
    size_t total = (size_t)B * N;
    size_t blockBase = (size_t)blockIdx.x * (TPB * DPT);
    int nanf = g_nanflag;

    // fast path: whole block inside one batch, full tile
    bool uniform = (blockBase + (size_t)(TPB * DPT) <= total) &&
                   ((N % (TPB * DPT)) == 0);

    if (uniform) {
        int b = (int)(blockBase / (size_t)N);
        float p0 = g_pose[b * 6 + 0], p1 = g_pose[b * 6 + 1], p2 = g_pose[b * 6 + 2];
        float p3 = g_pose[b * 6 + 3], p4 = g_pose[b * 6 + 4], p5 = g_pose[b * 6 + 5];

#pragma unroll
        for (int k = 0; k < DPT; k++) {
            size_t idx = blockBase + (size_t)k * TPB + threadIdx.x;  // coalesced
            float4 s0 = __ldcs(&g_s0[idx]);
            float4 s1 = __ldcs(&g_s1[idx]);
            float v = s0.x * p0 + s0.y * p1 + s0.z * p2
                    + s0.w * p3 + s1.x * p4 + s1.y * p5;
            float d = s1.w * (s1.z - v);
            d = fminf(fmaxf(d, -5.0f), 5.0f);
            out[(size_t)B * 6 + idx] = nanf ? 0.0f : d;
        }
    } else {
#pragma unroll
        for (int k = 0; k < DPT; k++) {
            size_t idx = blockBase + (size_t)k * TPB + threadIdx.x;
            if (idx >= total) continue;
            int b = (int)(idx / (size_t)N);
            float4 s0 = __ldcs(&g_s0[idx]);
            float4 s1 = __ldcs(&g_s1[idx]);
            float v = s0.x * g_pose[b * 6 + 0] + s0.y * g_pose[b * 6 + 1]
                    + s0.z * g_pose[b * 6 + 2] + s0.w * g_pose[b * 6 + 3]
                    + s1.x * g_pose[b * 6 + 4] + s1.y * g_pose[b * 6 + 5];
            float d = s1.w * (s1.z - v);
            d = fminf(fmaxf(d, -5.0f), 5.0f);
            out[(size_t)B * 6 + idx] = nanf ? 0.0f : d;
        }
    }
}

extern "C" void kernel_launch(void* const* d_in, const int* in_sizes, int n_in,
                              void* d_out, int out_size)
{
    const float* r      = (const float*)d_in[0];
    const float* w      = (const float*)d_in[1];
    const float* Jp     = (const float*)d_in[2];
    const float* Jd     = (const float*)d_in[3];
    const float* lmbda  = (const float*)d_in[4];
    const int*   iter_i = (const int*)d_in[5];
    float* out = (float*)d_out;

    int B = in_sizes[4];
    int N = in_sizes[0] / (2 * B);

    int tile   = TPB * ITER;
    int chunks = (N + tile - 1) / tile;

    dim3 g1(chunks, B);
    pass1_kernel<<<g1, TPB>>>(r, w, Jp, Jd, lmbda, iter_i, out, N, B);

    size_t total = (size_t)B * N;
    size_t tpg = (size_t)TPB * DPT;
    int blocks = (int)((total + tpg - 1) / tpg);
    depth_kernel<<<blocks, TPB>>>(out, N, B);
}

// round 7
// speedup vs baseline: 1.2121x; 1.0722x over previous
#include <cuda_runtime.h>
#include <math.h>

// ---------------------------------------------------------------------------
// DBASolver: B=16, N=131072, C=2, P=6.  Single persistent kernel:
//   phase 1: per-node H_pd/g_d/inv -> SoA scratch + 27-scalar per-(block,batch)
//            partial reduction (each block owns a contiguous range of 1 batch)
//   phase 2: last-arriving block reduces partials + 16x damped 6x6 solve,
//            publishes pose via epoch counter
//   phase 3: all blocks spin on epoch, then compute delta_depth on the SAME
//            (batch, range) they produced in phase 1 (L2-warm scratch).
// Grid (27, B) = 432 blocks; __launch_bounds__(256, 3) guarantees 3 blocks/SM
// (reg cap 85, smem ~2.6KB) -> 432 <= 444 resident, spin cannot deadlock.
// ---------------------------------------------------------------------------

#define MAXB  16
#define MAXN  131072
#define TPB   256
#define RBLK  27          // range-blocks per batch; 27*16 = 432 <= 444 resident
#define UNROLL 4

// SoA per-node scratch: s0 = {hpd0..3}, s1 = {hpd4, hpd5, g_d, inv}
__device__ float4   g_s0[(size_t)MAXB * MAXN];
__device__ float4   g_s1[(size_t)MAXB * MAXN];
__device__ float    g_partial[(size_t)MAXB * RBLK * 27];
__device__ float    g_pose[MAXB * 6];
__device__ int      g_nanflag;
__device__ unsigned g_done;    // wraps to 0 each launch via atomicInc(total-1)
__device__ unsigned g_epoch;   // monotonically increasing across replays

__device__ __forceinline__ void node_body(
    size_t idx, float safe_l,
    const float4* __restrict__ Jp4, const float2* __restrict__ r2,
    const float2* __restrict__ w2,  const float2* __restrict__ jd2,
    float acc[27])
{
    float4 jpA = __ldcs(&Jp4[idx * 3 + 0]);
    float4 jpB = __ldcs(&Jp4[idx * 3 + 1]);
    float4 jpC = __ldcs(&Jp4[idx * 3 + 2]);
    float2 rv  = __ldcs(&r2[idx]);
    float2 wv  = __ldcs(&w2[idx]);
    float2 jdv = __ldcs(&jd2[idx]);

    float conf = wv.x, nl = wv.y;
    float jp0[6] = { jpA.x, jpA.y, jpA.z, jpA.w, jpB.x, jpB.y };
    float jp1[6] = { jpB.z, jpB.w, jpC.x, jpC.y, jpC.z, jpC.w };

    float hpd[6];
#pragma unroll
    for (int p = 0; p < 6; p++)
        hpd[p] = conf * (jp0[p] * jdv.x + jp1[p] * jdv.y);

    float hdd = conf * (jdv.x * jdv.x + jdv.y * jdv.y);
    float gd  = conf * (jdv.x * rv.x  + jdv.y * rv.y);
    float inv = 1.0f / fmaxf(hdd + safe_l + nl + 1e-4f, 1e-4f);

    // coalesced SoA scratch stores (16B lane stride)
    g_s0[idx] = make_float4(hpd[0], hpd[1], hpd[2], hpd[3]);
    g_s1[idx] = make_float4(hpd[4], hpd[5], gd, inv);

    int k = 0;
#pragma unroll
    for (int p = 0; p < 6; p++) {
        float cjp0p = conf * jp0[p];
        float cjp1p = conf * jp1[p];
        float tp    = inv  * hpd[p];
#pragma unroll
        for (int q = p; q < 6; q++) {
            float a = acc[k];
            a = fmaf(cjp0p, jp0[q], a);
            a = fmaf(cjp1p, jp1[q], a);
            a = fmaf(-tp,   hpd[q], a);
            acc[k++] = a;
        }
        float gp = cjp0p * rv.x + cjp1p * rv.y;
        acc[21 + p] += gp - tp * gd;
    }
}

__global__ void __launch_bounds__(TPB, 3)
dba_kernel(const float* __restrict__ r, const float* __restrict__ w,
           const float* __restrict__ Jp, const float* __restrict__ Jd,
           const float* __restrict__ lmbda, const int* __restrict__ iter_idx,
           float* __restrict__ out, int N, int B)
{
    const int rblk = blockIdx.x;          // 0..RBLK-1
    const int b    = blockIdx.y;          // 0..B-1
    const unsigned total_blocks = gridDim.x * gridDim.y;

    // epoch snapshot BEFORE any work (all blocks resident from t=0; the
    // increment happens only after all blocks' atomicInc below)
    unsigned epoch0 = *(volatile unsigned*)&g_epoch;

    const size_t bn0 = (size_t)b * N;
    int npb   = (N + RBLK - 1) / RBLK;
    int start = rblk * npb;
    int end   = min(N, start + npb);

    float lm = lmbda[b];
    float safe_l = isnan(lm) ? 100.0f : lm;
    safe_l = fmaxf(safe_l, 0.001f);

    const float4* __restrict__ Jp4 = (const float4*)Jp;
    const float2* __restrict__ r2  = (const float2*)r;
    const float2* __restrict__ w2  = (const float2*)w;
    const float2* __restrict__ jd2 = (const float2*)Jd;

    float acc[27];
#pragma unroll
    for (int i = 0; i < 27; i++) acc[i] = 0.0f;

    // ---- phase 1: main loop, unguarded 4x unroll --------------------------
    int n0 = start;
    for (; n0 + UNROLL * TPB <= end; n0 += UNROLL * TPB) {
#pragma unroll
        for (int u = 0; u < UNROLL; u++) {
            size_t n = (size_t)n0 + u * TPB + threadIdx.x;
            node_body(bn0 + n, safe_l, Jp4, r2, w2, jd2, acc);
        }
    }
    for (; n0 < end; n0 += TPB) {
        int n = n0 + threadIdx.x;
        if (n < end)
            node_body(bn0 + n, safe_l, Jp4, r2, w2, jd2, acc);
    }

    // warp reduce 27 values
#pragma unroll
    for (int i = 0; i < 27; i++) {
#pragma unroll
        for (int off = 16; off > 0; off >>= 1)
            acc[i] += __shfl_down_sync(0xFFFFFFFFu, acc[i], off);
    }

    __shared__ float sred[TPB / 32][27];
    int warp = threadIdx.x >> 5, lane = threadIdx.x & 31;
    if (lane == 0) {
#pragma unroll
        for (int i = 0; i < 27; i++) sred[warp][i] = acc[i];
    }
    __syncthreads();

    if (threadIdx.x < 27) {
        float s = 0.0f;
#pragma unroll
        for (int wd = 0; wd < TPB / 32; wd++) s += sred[wd][threadIdx.x];
        g_partial[((size_t)b * RBLK + rblk) * 27 + threadIdx.x] = s;
    }
    __syncthreads();

    // ---- phase 2: last block reduces + solves -----------------------------
    __shared__ bool s_last;
    if (threadIdx.x == 0) {
        __threadfence();
        unsigned old = atomicInc(&g_done, total_blocks - 1);
        s_last = (old == total_blocks - 1);
    }
    __syncthreads();

    if (s_last) {
        __shared__ float sH[MAXB][27];
        __shared__ int   s_nan;
        int t = threadIdx.x;
        if (t == 0) s_nan = 0;

        for (int slot = t; slot < B * 27; slot += TPB) {
            int bb = slot / 27, i = slot % 27;
            float s = 0.0f;
            for (int c = 0; c < RBLK; c++)
                s += g_partial[((size_t)bb * RBLK + c) * 27 + i];
            sH[bb][i] = s;
        }
        __syncthreads();

        int bb = t;
        if (bb < B) {
            float lm2 = lmbda[bb];
            float sl = isnan(lm2) ? 100.0f : lm2;
            sl = fmaxf(sl, 0.001f);

            float H[6][6], g[6];
            int k = 0;
            for (int p = 0; p < 6; p++)
                for (int q = p; q < 6; q++) { float v = sH[bb][k++]; H[p][q] = v; H[q][p] = v; }
            for (int p = 0; p < 6; p++) g[p] = sH[bb][21 + p];

            for (int i = 0; i < 6; i++) H[i][i] += sl;

            if (iter_idx[0] >= 2) {
                for (int p = 3; p < 6; p++) g[p] = 0.0f;
                for (int p = 3; p < 6; p++)
                    for (int q = 3; q < 6; q++) H[p][q] += 1.0e8f;
            }
            for (int i = 0; i < 6; i++) H[i][i] += 1.0f;
            for (int i = 0; i < 6; i++) H[i][i] += 0.01f * H[i][i];

            // 6x6 solve, double, partial pivoting
            double A[6][7];
            for (int i = 0; i < 6; i++) {
                for (int j = 0; j < 6; j++) A[i][j] = (double)H[i][j];
                A[i][6] = (double)g[i];
            }
            for (int c = 0; c < 6; c++) {
                int piv = c; double mx = fabs(A[c][c]);
                for (int rr = c + 1; rr < 6; rr++) {
                    double a = fabs(A[rr][c]);
                    if (a > mx) { mx = a; piv = rr; }
                }
                if (piv != c) {
                    for (int j = c; j < 7; j++) {
                        double tmp = A[c][j]; A[c][j] = A[piv][j]; A[piv][j] = tmp;
                    }
                }
                double dinv = 1.0 / A[c][c];
                for (int rr = c + 1; rr < 6; rr++) {
                    double f = A[rr][c] * dinv;
                    for (int j = c; j < 7; j++) A[rr][j] -= f * A[c][j];
                }
            }
            double x[6];
            for (int i = 5; i >= 0; i--) {
                double s = A[i][6];
                for (int j = i + 1; j < 6; j++) s -= A[i][j] * x[j];
                x[i] = s / A[i][i];
            }

            bool anynan = false;
            float pose[6];
            for (int p = 0; p < 6; p++) {
                pose[p] = (float)x[p];
                g_pose[bb * 6 + p] = pose[p];
                if (isnan(pose[p])) anynan = true;
            }
            if (anynan) atomicOr(&s_nan, 1);
            for (int p = 0; p < 6; p++) sH[bb][p] = pose[p];
        }
        __syncthreads();

        if (t == 0) g_nanflag = s_nan;
        if (bb < B) {
            for (int p = 0; p < 6; p++) {
                float v = fminf(fmaxf(sH[bb][p], -2.0f), 2.0f);
                out[bb * 6 + p] = s_nan ? 0.0f : v;
            }
        }
        __threadfence();
        __syncthreads();
        if (t == 0) atomicAdd(&g_epoch, 1u);   // release: pose published
    }

    // ---- phase 3: wait for pose, then depth on our own (b, range) ---------
    if (threadIdx.x == 0) {
        while (*(volatile unsigned*)&g_epoch == epoch0)
            __nanosleep(64);
    }
    __syncthreads();
    __threadfence();   // acquire

    float p0 = __ldcg(&g_pose[b * 6 + 0]);
    float p1 = __ldcg(&g_pose[b * 6 + 1]);
    float p2 = __ldcg(&g_pose[b * 6 + 2]);
    float p3 = __ldcg(&g_pose[b * 6 + 3]);
    float p4 = __ldcg(&g_pose[b * 6 + 4]);
    float p5 = __ldcg(&g_pose[b * 6 + 5]);
    int nanf = __ldcg(&g_nanflag);

    float* dout = out + (size_t)B * 6 + bn0;
    for (int n = start + threadIdx.x; n < end; n += TPB) {
        size_t idx = bn0 + n;
        float4 s0 = g_s0[idx];
        float4 s1 = g_s1[idx];
        float v = s0.x * p0 + s0.y * p1 + s0.z * p2
                + s0.w * p3 + s1.x * p4 + s1.y * p5;
        float d = s1.w * (s1.z - v);
        d = fminf(fmaxf(d, -5.0f), 5.0f);
        dout[n] = nanf ? 0.0f : d;
    }
}

extern "C" void kernel_launch(void* const* d_in, const int* in_sizes, int n_in,
                              void* d_out, int out_size)
{
    const float* r      = (const float*)d_in[0];
    const float* w      = (const float*)d_in[1];
    const float* Jp     = (const float*)d_in[2];
    const float* Jd     = (const float*)d_in[3];
    const float* lmbda  = (const float*)d_in[4];
    const int*   iter_i = (const int*)d_in[5];
    float* out = (float*)d_out;

    int B = in_sizes[4];
    int N = in_sizes[0] / (2 * B);

    dim3 grid(RBLK, B);
    dba_kernel<<<grid, TPB>>>(r, w, Jp, Jd, lmbda, iter_i, out, N, B);
}